// round 1
// baseline (speedup 1.0000x reference)
#include <cuda_runtime.h>
#include <math.h>

#define C_CH 256
#define OUTD 7
#define NBIN 49

// Channels-last scratch for the 4 FPN levels (B=2 fixed by problem).
__device__ float g_t0[2 * 200 * 200 * C_CH];
__device__ float g_t1[2 * 100 * 100 * C_CH];
__device__ float g_t2[2 * 50  * 50  * C_CH];
__device__ float g_t3[2 * 25  * 25  * C_CH];

// [B,C,HW] -> [B,HW,C] tiled transpose. level selects destination scratch.
__global__ void transpose_k(const float* __restrict__ in, int HW, int level) {
    __shared__ float tile[32][33];
    float* outp = (level == 0) ? g_t0 : (level == 1) ? g_t1 : (level == 2) ? g_t2 : g_t3;
    int b  = blockIdx.z;
    int p0 = blockIdx.x * 32;
    int c0 = blockIdx.y * 32;
    const float* ib = in + (size_t)b * C_CH * HW;
    float* ob       = outp + (size_t)b * C_CH * HW;
    int tx = threadIdx.x, ty = threadIdx.y;

    #pragma unroll
    for (int i = ty; i < 32; i += 8) {
        int p = p0 + tx;
        tile[i][tx] = (p < HW) ? ib[(size_t)(c0 + i) * HW + p] : 0.0f;
    }
    __syncthreads();
    #pragma unroll
    for (int i = ty; i < 32; i += 8) {
        int p = p0 + i;
        if (p < HW) ob[(size_t)p * C_CH + (c0 + tx)] = tile[tx][i];
    }
}

// One block per box. thread = channel. Lanes read consecutive channels
// (channels-last) => every tap load is one coalesced 128B line.
// Per-box output staged in shared so global writes are coalesced.
__global__ __launch_bounds__(256) void roi_main(const float* __restrict__ props,
                                                float* __restrict__ out,
                                                int B, int Np) {
    extern __shared__ float sh[];            // NBIN * 256 staging
    __shared__ int   s_lo[28], s_hi[28];     // [0..13]=y, [14..27]=x
    __shared__ float s_fr[28], s_va[28];

    int n = blockIdx.x;
    int t = threadIdx.x;

    float bx0 = props[n * 4 + 0];
    float by0 = props[n * 4 + 1];
    float bx1 = props[n * 4 + 2];
    float by1 = props[n * 4 + 3];

    // level selection: floor(4 + log2(s/224 + 1e-6)), clip [2,5], -2
    float s  = sqrtf((bx1 - bx0) * (by1 - by0));
    float lv = floorf(4.0f + log2f(s * (1.0f / 224.0f) + 1e-6f));
    lv = fminf(fmaxf(lv, 2.0f), 5.0f);
    int l = (int)lv - 2;

    int H;
    float scale;
    const float* fp;
    if      (l == 0) { H = 200; scale = 0.25f;    fp = g_t0; }
    else if (l == 1) { H = 100; scale = 0.125f;   fp = g_t1; }
    else if (l == 2) { H = 50;  scale = 0.0625f;  fp = g_t2; }
    else             { H = 25;  scale = 0.03125f; fp = g_t3; }
    int W = H;
    int bidx = n / Np;

    // Precompute sample interpolation data (14 y-samples, 14 x-samples).
    if (t < 28) {
        int  k   = (t < 14) ? t : (t - 14);
        bool isY = (t < 14);
        // off[k] = (k>>1) + ((k&1)+0.5)/2
        float off = (float)(k >> 1) + ((float)(k & 1) + 0.5f) * 0.5f;
        float c0  = (isY ? by0 : bx0) * scale;
        float c1  = (isY ? by1 : bx1) * scale;
        float bin = fmaxf(c1 - c0, 1.0f) * (1.0f / 7.0f);
        float c   = c0 + off * bin;
        int   sz  = H;  // square maps
        float valid = (c >= -1.0f && c <= (float)sz) ? 1.0f : 0.0f;
        float cc  = fmaxf(c, 0.0f);
        int   lo0 = (int)floorf(cc);
        bool  edge = (lo0 >= sz - 1);
        s_lo[t] = edge ? (sz - 1) : lo0;
        s_hi[t] = edge ? (sz - 1) : (lo0 + 1);
        s_fr[t] = edge ? 0.0f : (cc - (float)lo0);
        s_va[t] = valid;
    }
    __syncthreads();

    const float* fb = fp + (size_t)bidx * H * W * C_CH + t;

    #pragma unroll 1
    for (int by = 0; by < 7; ++by) {
        int   yl[2], yrow_l[2], yrow_h[2];
        float fy[2], vy[2];
        #pragma unroll
        for (int sy = 0; sy < 2; ++sy) {
            int ky = 2 * by + sy;
            yl[sy]     = s_lo[ky];
            yrow_l[sy] = s_lo[ky] * W;
            yrow_h[sy] = s_hi[ky] * W;
            fy[sy]     = s_fr[ky];
            vy[sy]     = s_va[ky];
        }
        #pragma unroll 1
        for (int bxi = 0; bxi < 7; ++bxi) {
            float acc = 0.0f;
            #pragma unroll
            for (int sx = 0; sx < 2; ++sx) {
                int   kx = 14 + 2 * bxi + sx;
                int   xl = s_lo[kx];
                int   xh = s_hi[kx];
                float lx = s_fr[kx];
                float vx = s_va[kx];
                float hx = 1.0f - lx;
                #pragma unroll
                for (int sy = 0; sy < 2; ++sy) {
                    float ly = fy[sy];
                    float hy = 1.0f - ly;
                    float m  = vy[sy] * vx;
                    float v00 = __ldg(fb + (yrow_l[sy] + xl) * C_CH);
                    float v01 = __ldg(fb + (yrow_l[sy] + xh) * C_CH);
                    float v10 = __ldg(fb + (yrow_h[sy] + xl) * C_CH);
                    float v11 = __ldg(fb + (yrow_h[sy] + xh) * C_CH);
                    acc += m * (hy * (hx * v00 + lx * v01) +
                                ly * (hx * v10 + lx * v11));
                }
            }
            sh[t * NBIN + by * 7 + bxi] = acc * 0.25f;
        }
    }
    __syncthreads();

    // Coalesced write of the whole box tile: layout matches out[n, c, 7, 7].
    float* ob = out + (size_t)n * (C_CH * NBIN);
    #pragma unroll 4
    for (int j = t; j < C_CH * NBIN; j += 256) ob[j] = sh[j];
}

extern "C" void kernel_launch(void* const* d_in, const int* in_sizes, int n_in,
                              void* d_out, int out_size) {
    const float* f0    = (const float*)d_in[0];
    const float* f1    = (const float*)d_in[1];
    const float* f2    = (const float*)d_in[2];
    const float* f3    = (const float*)d_in[3];
    const float* props = (const float*)d_in[4];

    int B  = in_sizes[0] / (C_CH * 200 * 200);
    int Np = in_sizes[4] / (4 * B);
    int Nb = B * Np;

    dim3 blk(32, 8);
    {
        int HW = 200 * 200;
        dim3 grd((HW + 31) / 32, C_CH / 32, B);
        transpose_k<<<grd, blk>>>(f0, HW, 0);
    }
    {
        int HW = 100 * 100;
        dim3 grd((HW + 31) / 32, C_CH / 32, B);
        transpose_k<<<grd, blk>>>(f1, HW, 1);
    }
    {
        int HW = 50 * 50;
        dim3 grd((HW + 31) / 32, C_CH / 32, B);
        transpose_k<<<grd, blk>>>(f2, HW, 2);
    }
    {
        int HW = 25 * 25;
        dim3 grd((HW + 31) / 32, C_CH / 32, B);
        transpose_k<<<grd, blk>>>(f3, HW, 3);
    }

    int smem = NBIN * C_CH * (int)sizeof(float);  // 50176 B > 48K default
    cudaFuncSetAttribute(roi_main, cudaFuncAttributeMaxDynamicSharedMemorySize, smem);
    roi_main<<<Nb, 256, smem>>>(props, (float*)d_out, B, Np);
}